// round 3
// baseline (speedup 1.0000x reference)
#include <cuda_runtime.h>
#include <math.h>

#define MAXB 4096
__device__ float    g_seg_bce[MAXB];   // zero-init at module load; last block re-zeroes
__device__ float    g_seg_cnt[MAXB];
__device__ unsigned g_ticket;          // zero-init; last block resets

__device__ __forceinline__ float bce_fast(float p, float t) {
    float lp = fmaxf(__logf(p),        -100.0f);   // __logf(0) = -inf -> -100
    float lq = fmaxf(__logf(1.0f - p), -100.0f);
    return -(t * lp + (1.0f - t) * lq);
}

__device__ __forceinline__ void proc4(float4 p4, float4 t4, int4 s4, int4 k4,
                                      float& b, float& m, int& slo, int& shi) {
    float m0 = (float)k4.x, m1 = (float)k4.y, m2 = (float)k4.z, m3 = (float)k4.w;
    float b0 = bce_fast(p4.x * m0, t4.x);
    float b1 = bce_fast(p4.y * m1, t4.y);
    float b2 = bce_fast(p4.z * m2, t4.z);
    float b3 = bce_fast(p4.w * m3, t4.w);
    b += (b0 + b1) + (b2 + b3);
    m += (m0 + m1) + (m2 + m3);
    slo = s4.x; shi = s4.w;
}

__device__ __forceinline__ void flush4(float4 p4, float4 t4, int4 s4, int4 k4) {
    // per-element atomics for mixed-segment groups
    float m0 = (float)k4.x, m1 = (float)k4.y, m2 = (float)k4.z, m3 = (float)k4.w;
    atomicAdd(&g_seg_bce[s4.x], bce_fast(p4.x * m0, t4.x)); atomicAdd(&g_seg_cnt[s4.x], m0);
    atomicAdd(&g_seg_bce[s4.y], bce_fast(p4.y * m1, t4.y)); atomicAdd(&g_seg_cnt[s4.y], m1);
    atomicAdd(&g_seg_bce[s4.z], bce_fast(p4.z * m2, t4.z)); atomicAdd(&g_seg_cnt[s4.z], m2);
    atomicAdd(&g_seg_bce[s4.w], bce_fast(p4.w * m3, t4.w)); atomicAdd(&g_seg_cnt[s4.w], m3);
}

__global__ void __launch_bounds__(256) fused_kernel(
        const float* __restrict__ pred,
        const float* __restrict__ tgt,
        const int*   __restrict__ batch,
        const int*   __restrict__ mask,
        const float* __restrict__ sat_p,
        const float* __restrict__ sat_t,
        float*       __restrict__ out,
        int n4, int N, int B, float l1)
{
    const unsigned FULL = 0xffffffffu;
    const float4* pred4  = (const float4*)pred;
    const float4* tgt4   = (const float4*)tgt;
    const int4*   batch4 = (const int4*)batch;
    const int4*   mask4  = (const int4*)mask;

    // ---- main phase: 2 adjacent float4 groups per thread ----
    int g0 = (blockIdx.x * blockDim.x + threadIdx.x) * 2;
    int g1 = g0 + 1;

    bool v0 = (g0 < n4), v1 = (g1 < n4);
    unsigned full_warp = __ballot_sync(FULL, v1);   // all 64 groups in range?

    if (v0) {
        float4 pA = pred4[g0], tA = tgt4[g0];
        int4   sA = batch4[g0], kA = mask4[g0];
        float4 pB; float4 tB; int4 sB; int4 kB;
        if (v1) { pB = pred4[g1]; tB = tgt4[g1]; sB = batch4[g1]; kB = mask4[g1]; }

        float b = 0.0f, m = 0.0f;
        int sloA, shiA, sloB = 0, shiB = 0;
        proc4(pA, tA, sA, kA, b, m, sloA, shiA);
        float bA = b, mA = m;
        if (v1) proc4(pB, tB, sB, kB, b, m, sloB, shiB);

        int myLo = sloA;
        int myHi = v1 ? shiB : shiA;

        int wlo = __shfl_sync(FULL, myLo, 0);
        int whi = __shfl_sync(FULL, myHi, 31);

        if (full_warp == FULL && wlo == whi) {
            // fast path: whole warp (256 nodes) in one segment
            #pragma unroll
            for (int o = 16; o; o >>= 1) {
                b += __shfl_down_sync(FULL, b, o);
                m += __shfl_down_sync(FULL, m, o);
            }
            if ((threadIdx.x & 31) == 0) {
                atomicAdd(&g_seg_bce[wlo], b);
                atomicAdd(&g_seg_cnt[wlo], m);
            }
        } else if (myLo == myHi) {
            atomicAdd(&g_seg_bce[myLo], b);
            atomicAdd(&g_seg_cnt[myLo], m);
        } else {
            if (sloA == shiA) { atomicAdd(&g_seg_bce[sloA], bA); atomicAdd(&g_seg_cnt[sloA], mA); }
            else              flush4(pA, tA, sA, kA);
            if (v1) {
                if (sloB == shiB) { atomicAdd(&g_seg_bce[sloB], b - bA); atomicAdd(&g_seg_cnt[sloB], m - mA); }
                else              flush4(pB, tB, sB, kB);
            }
        }
    }

    // scalar tail (N % 4), handled by block 0
    int tail = N - (n4 << 2);
    if (blockIdx.x == 0 && threadIdx.x < tail) {
        int i = (n4 << 2) + threadIdx.x;
        float mm = (float)mask[i];
        atomicAdd(&g_seg_bce[batch[i]], bce_fast(pred[i] * mm, tgt[i]));
        atomicAdd(&g_seg_cnt[batch[i]], mm);
    }

    // ---- last-block epilogue ----
    __shared__ int sh_last;
    __shared__ float sh[32];
    __syncthreads();
    __threadfence();
    if (threadIdx.x == 0) {
        unsigned t = atomicAdd(&g_ticket, 1u);
        sh_last = (t == gridDim.x - 1) ? 1 : 0;
    }
    __syncthreads();
    if (!sh_last) return;

    float acc = 0.0f, sat = 0.0f;
    for (int i = threadIdx.x; i < B; i += blockDim.x) {
        float c  = __ldcg(&g_seg_cnt[i]);
        float sb = __ldcg(&g_seg_bce[i]);
        acc += (c > 0.0f) ? (sb / fmaxf(c, 1.0f)) : 0.0f;
        sat += bce_fast(sat_p[i], sat_t[i]);
        g_seg_cnt[i] = 0.0f;                 // re-zero for next graph replay
        g_seg_bce[i] = 0.0f;
    }
    float v = acc + sat * (l1 / (float)B);
    #pragma unroll
    for (int o = 16; o; o >>= 1) v += __shfl_down_sync(FULL, v, o);
    int lane = threadIdx.x & 31, wid = threadIdx.x >> 5;
    if (lane == 0) sh[wid] = v;
    __syncthreads();
    if (wid == 0) {
        int nw = (blockDim.x + 31) >> 5;
        v = (lane < nw) ? sh[lane] : 0.0f;
        #pragma unroll
        for (int o = 16; o; o >>= 1) v += __shfl_down_sync(FULL, v, o);
        if (lane == 0) {
            out[0] = v;
            atomicExch(&g_ticket, 0u);       // reset for next replay
        }
    }
}

extern "C" void kernel_launch(void* const* d_in, const int* in_sizes, int n_in,
                              void* d_out, int out_size) {
    const float* y_mus_pred = (const float*)d_in[0];
    const float* y_mus      = (const float*)d_in[1];
    const float* y_sat_pred = (const float*)d_in[2];
    const float* y_sat      = (const float*)d_in[3];
    const int*   batch      = (const int*)  d_in[4];
    const int*   mask       = (const int*)  d_in[5];
    int N = in_sizes[0];
    int B = in_sizes[2];
    float L1 = 1.0f / 50.0f;

    int n4 = N >> 2;
    int groups_per_block = 256 * 2;
    int blocks = (n4 + groups_per_block - 1) / groups_per_block;
    if (blocks < 1) blocks = 1;

    fused_kernel<<<blocks, 256>>>(y_mus_pred, y_mus, batch, mask,
                                  y_sat_pred, y_sat, (float*)d_out,
                                  n4, N, B, L1);
}